// round 1
// baseline (speedup 1.0000x reference)
#include <cuda_runtime.h>
#include <cmath>

// ---------------------------------------------------------------------------
// SwinTransformerBlock: B=8, H=W=128, C=256, heads=8, d=32, ws=8, shift=4
// Tokens M = 8*128*128 = 131072.  hidden = 1024.
// Pipeline:
//   1. LN1(x) -> g_xn
//   2. qkv = g_xn @ qkv_w^T + qkv_b          [131072 x 768]
//   3. windowed shifted attention (fused)    -> g_ao (token order)
//   4. x2 = x + g_ao @ proj_w^T + proj_b
//   5. y  = LN2(x2) -> g_xn (reuse)
//   6. h  = gelu(y @ fc1_w^T + fc1_b)        [131072 x 1024]
//   7. out = x2 + h @ fc2_w^T + fc2_b
// ---------------------------------------------------------------------------

#define M_TOK 131072
#define CDIM  256
#define HID   1024

__device__ float g_xn [M_TOK * CDIM];   // 128 MB
__device__ float g_qkv[M_TOK * 3*CDIM]; // 384 MB
__device__ float g_ao [M_TOK * CDIM];   // 128 MB
__device__ float g_x2 [M_TOK * CDIM];   // 128 MB
__device__ float g_hid[M_TOK * HID];    // 512 MB

// ---------------------------------------------------------------------------
// LayerNorm: one warp per row of 256.
// ---------------------------------------------------------------------------
__global__ __launch_bounds__(256) void ln_kernel(
    const float* __restrict__ x, const float* __restrict__ g,
    const float* __restrict__ b, float* __restrict__ out)
{
    long row  = (long)blockIdx.x * 8 + (threadIdx.x >> 5);
    int  lane = threadIdx.x & 31;
    const float* xr = x + row * CDIM + lane * 8;
    float4 v0 = *(const float4*)(xr);
    float4 v1 = *(const float4*)(xr + 4);

    float s  = v0.x+v0.y+v0.z+v0.w + v1.x+v1.y+v1.z+v1.w;
    float sq = v0.x*v0.x+v0.y*v0.y+v0.z*v0.z+v0.w*v0.w
             + v1.x*v1.x+v1.y*v1.y+v1.z*v1.z+v1.w*v1.w;
    #pragma unroll
    for (int o = 16; o > 0; o >>= 1) {
        s  += __shfl_xor_sync(0xffffffffu, s,  o);
        sq += __shfl_xor_sync(0xffffffffu, sq, o);
    }
    float mean = s  * (1.0f / 256.0f);
    float var  = sq * (1.0f / 256.0f) - mean * mean;
    float rstd = rsqrtf(var + 1e-5f);

    const float4 g0 = *(const float4*)(g + lane*8);
    const float4 g1 = *(const float4*)(g + lane*8 + 4);
    const float4 b0 = *(const float4*)(b + lane*8);
    const float4 b1 = *(const float4*)(b + lane*8 + 4);

    float4 o0, o1;
    o0.x = (v0.x-mean)*rstd*g0.x + b0.x;  o0.y = (v0.y-mean)*rstd*g0.y + b0.y;
    o0.z = (v0.z-mean)*rstd*g0.z + b0.z;  o0.w = (v0.w-mean)*rstd*g0.w + b0.w;
    o1.x = (v1.x-mean)*rstd*g1.x + b1.x;  o1.y = (v1.y-mean)*rstd*g1.y + b1.y;
    o1.z = (v1.z-mean)*rstd*g1.z + b1.z;  o1.w = (v1.w-mean)*rstd*g1.w + b1.w;

    float* orow = out + row * CDIM + lane * 8;
    *(float4*)(orow)     = o0;
    *(float4*)(orow + 4) = o1;
}

// ---------------------------------------------------------------------------
// SGEMM: C[M,N] = A[M,K] @ B[N,K]^T + bias[N] (+gelu) (+res[M,N])
// BM=128, BN=64, BK=16, 256 threads, 8x4 microtile.
// M fixed = 131072 (grid.y = 1024), N,K runtime (multiples of 64 / 16).
// ---------------------------------------------------------------------------
__device__ __forceinline__ float gelu_f(float v) {
    return 0.5f * v * (1.0f + erff(v * 0.7071067811865476f));
}

template<bool GELU, bool RES>
__global__ __launch_bounds__(256) void gemm_kernel(
    const float* __restrict__ A, const float* __restrict__ B,
    const float* __restrict__ bias, const float* __restrict__ res,
    float* __restrict__ C, int N, int K)
{
    __shared__ __align__(16) float As[16 * 132];
    __shared__ __align__(16) float Bs[16 * 68];

    const int tid = threadIdx.x;
    const int tx = tid & 15;        // 16 * 4 = 64 cols
    const int ty = tid >> 4;        // 16 * 8 = 128 rows
    const long gr0 = (long)blockIdx.y * 128;
    const int  gc0 = blockIdx.x * 64;

    const int arow = tid >> 2;      // 0..63
    const int ac4  = tid & 3;       // 0..3 (float4 within 16-wide k slab)

    float acc[8][4];
    #pragma unroll
    for (int i = 0; i < 8; i++)
        #pragma unroll
        for (int j = 0; j < 4; j++) acc[i][j] = 0.0f;

    for (int k0 = 0; k0 < K; k0 += 16) {
        float4 av0 = *(const float4*)(A + (gr0 + arow)      * K + k0 + ac4*4);
        float4 av1 = *(const float4*)(A + (gr0 + arow + 64) * K + k0 + ac4*4);
        float4 bv  = *(const float4*)(B + (long)(gc0 + arow) * K + k0 + ac4*4);
        __syncthreads();
        As[(ac4*4+0)*132 + arow] = av0.x;
        As[(ac4*4+1)*132 + arow] = av0.y;
        As[(ac4*4+2)*132 + arow] = av0.z;
        As[(ac4*4+3)*132 + arow] = av0.w;
        As[(ac4*4+0)*132 + arow + 64] = av1.x;
        As[(ac4*4+1)*132 + arow + 64] = av1.y;
        As[(ac4*4+2)*132 + arow + 64] = av1.z;
        As[(ac4*4+3)*132 + arow + 64] = av1.w;
        Bs[(ac4*4+0)*68 + arow] = bv.x;
        Bs[(ac4*4+1)*68 + arow] = bv.y;
        Bs[(ac4*4+2)*68 + arow] = bv.z;
        Bs[(ac4*4+3)*68 + arow] = bv.w;
        __syncthreads();

        #pragma unroll
        for (int kk = 0; kk < 16; kk++) {
            float4 a0 = *(const float4*)&As[kk*132 + ty*8];
            float4 a1 = *(const float4*)&As[kk*132 + ty*8 + 4];
            float4 b0 = *(const float4*)&Bs[kk*68 + tx*4];
            float ar[8] = {a0.x,a0.y,a0.z,a0.w,a1.x,a1.y,a1.z,a1.w};
            float br[4] = {b0.x,b0.y,b0.z,b0.w};
            #pragma unroll
            for (int i = 0; i < 8; i++)
                #pragma unroll
                for (int j = 0; j < 4; j++)
                    acc[i][j] += ar[i] * br[j];
        }
    }

    const float4 bb = *(const float4*)(bias + gc0 + tx*4);
    #pragma unroll
    for (int i = 0; i < 8; i++) {
        long row = gr0 + ty*8 + i;
        float4 o;
        o.x = acc[i][0] + bb.x;
        o.y = acc[i][1] + bb.y;
        o.z = acc[i][2] + bb.z;
        o.w = acc[i][3] + bb.w;
        if (GELU) {
            o.x = gelu_f(o.x); o.y = gelu_f(o.y);
            o.z = gelu_f(o.z); o.w = gelu_f(o.w);
        }
        if (RES) {
            float4 r = *(const float4*)(res + row * N + gc0 + tx*4);
            o.x += r.x; o.y += r.y; o.z += r.z; o.w += r.w;
        }
        *(float4*)(C + row * N + gc0 + tx*4) = o;
    }
}

// ---------------------------------------------------------------------------
// Fused shifted-window attention. One block per (window, head).
// grid = (8 heads, 2048 windows), 256 threads.
// Gathers q/k/v from token order (shift folded into index math), computes
// 64x64 scores + rel-pos bias + window mask, softmax, attn@v, scatters back.
// ---------------------------------------------------------------------------
__global__ __launch_bounds__(256) void attn_kernel(
    const float* __restrict__ qkv, const float* __restrict__ mask,
    const float* __restrict__ bt, float* __restrict__ ao)
{
    __shared__ __align__(16) float sq[64*32];
    __shared__ __align__(16) float sk[64*32];
    __shared__ __align__(16) float sv[64*32];
    __shared__ float ss[64*65];

    const int head = blockIdx.x;
    const int w    = blockIdx.y;
    const int bimg = w >> 8;     // batch
    const int wimg = w & 255;    // window index within image (nW=256)
    const int wh   = wimg >> 4;
    const int ww   = wimg & 15;
    const int tid  = threadIdx.x;

    // ---- gather q, k, v : 3 * 64 rows * 8 float4 = 1536 float4 loads ----
    for (int f = tid; f < 1536; f += 256) {
        int matn = f >> 9;          // 0=q 1=k 2=v
        int r    = (f >> 3) & 63;   // window token
        int c4   = f & 7;           // float4 within d=32
        int i = r >> 3, j = r & 7;
        int oh = (wh*8 + i + 4) & 127;
        int ow = (ww*8 + j + 4) & 127;
        long tok = (long)bimg * 16384 + oh * 128 + ow;
        float4 v = *(const float4*)(qkv + tok*768 + matn*256 + head*32 + c4*4);
        float* dst = (matn == 0 ? sq : (matn == 1 ? sk : sv)) + r*32 + c4*4;
        *(float4*)dst = v;
    }
    __syncthreads();

    // ---- scores: 4x4 tile per thread over 64x64 ----
    const int tn = (tid >> 4) * 4;
    const int tm = (tid & 15) * 4;
    float acc[4][4];
    #pragma unroll
    for (int i = 0; i < 4; i++)
        #pragma unroll
        for (int j = 0; j < 4; j++) acc[i][j] = 0.0f;

    #pragma unroll
    for (int d4 = 0; d4 < 8; d4++) {
        float4 qv[4], kv[4];
        #pragma unroll
        for (int i = 0; i < 4; i++) qv[i] = *(const float4*)&sq[(tn+i)*32 + d4*4];
        #pragma unroll
        for (int j = 0; j < 4; j++) kv[j] = *(const float4*)&sk[(tm+j)*32 + d4*4];
        #pragma unroll
        for (int i = 0; i < 4; i++)
            #pragma unroll
            for (int j = 0; j < 4; j++)
                acc[i][j] += qv[i].x*kv[j].x + qv[i].y*kv[j].y
                           + qv[i].z*kv[j].z + qv[i].w*kv[j].w;
    }

    const float scale = 0.17677669529663689f;   // 32^-0.5
    const float* mrow = mask + (long)wimg * 4096;
    #pragma unroll
    for (int i = 0; i < 4; i++) {
        #pragma unroll
        for (int j = 0; j < 4; j++) {
            int n = tn + i, m = tm + j;
            int ridx = ((n>>3) - (m>>3) + 7) * 15 + ((n&7) - (m&7) + 7);
            ss[n*65 + m] = acc[i][j]*scale + bt[ridx*8 + head] + mrow[n*64 + m];
        }
    }
    __syncthreads();

    // ---- softmax: one thread per row ----
    if (tid < 64) {
        float* r = &ss[tid*65];
        float mx = r[0];
        #pragma unroll 8
        for (int m = 1; m < 64; m++) mx = fmaxf(mx, r[m]);
        float sum = 0.0f;
        #pragma unroll 8
        for (int m = 0; m < 64; m++) { float e = __expf(r[m]-mx); r[m] = e; sum += e; }
        float inv = 1.0f / sum;
        #pragma unroll 8
        for (int m = 0; m < 64; m++) r[m] *= inv;
    }
    __syncthreads();

    // ---- out = attn @ v, scatter back to token order ----
    for (int u = tid; u < 512; u += 256) {
        int n = u >> 3, dd4 = u & 7;
        float4 a = make_float4(0.f, 0.f, 0.f, 0.f);
        #pragma unroll 8
        for (int m = 0; m < 64; m++) {
            float wgt = ss[n*65 + m];
            float4 vv = *(const float4*)&sv[m*32 + dd4*4];
            a.x += wgt*vv.x; a.y += wgt*vv.y; a.z += wgt*vv.z; a.w += wgt*vv.w;
        }
        int i = n >> 3, j = n & 7;
        int oh = (wh*8 + i + 4) & 127;
        int ow = (ww*8 + j + 4) & 127;
        long tok = (long)bimg * 16384 + oh * 128 + ow;
        *(float4*)(ao + tok*256 + head*32 + dd4*4) = a;
    }
}

// ---------------------------------------------------------------------------
extern "C" void kernel_launch(void* const* d_in, const int* in_sizes, int n_in,
                              void* d_out, int out_size)
{
    const float* x     = (const float*)d_in[0];
    const float* mask  = (const float*)d_in[1];
    const float* n1g   = (const float*)d_in[2];
    const float* n1b   = (const float*)d_in[3];
    const float* qkvw  = (const float*)d_in[4];
    const float* qkvb  = (const float*)d_in[5];
    const float* relb  = (const float*)d_in[6];
    const float* projw = (const float*)d_in[7];
    const float* projb = (const float*)d_in[8];
    const float* n2g   = (const float*)d_in[9];
    const float* n2b   = (const float*)d_in[10];
    const float* fc1w  = (const float*)d_in[11];
    const float* fc1b  = (const float*)d_in[12];
    const float* fc2w  = (const float*)d_in[13];
    const float* fc2b  = (const float*)d_in[14];
    float* out = (float*)d_out;

    float *xn, *qkv, *ao, *x2, *hid;
    cudaGetSymbolAddress((void**)&xn,  g_xn);
    cudaGetSymbolAddress((void**)&qkv, g_qkv);
    cudaGetSymbolAddress((void**)&ao,  g_ao);
    cudaGetSymbolAddress((void**)&x2,  g_x2);
    cudaGetSymbolAddress((void**)&hid, g_hid);

    // 1. LN1
    ln_kernel<<<M_TOK/8, 256>>>(x, n1g, n1b, xn);
    // 2. QKV projection: [131072,256] @ [768,256]^T
    gemm_kernel<false,false><<<dim3(768/64, M_TOK/128), 256>>>(
        xn, qkvw, qkvb, nullptr, qkv, 768, 256);
    // 3. windowed attention
    attn_kernel<<<dim3(8, 2048), 256>>>(qkv, mask, relb, ao);
    // 4. proj + residual(x)
    gemm_kernel<false,true><<<dim3(256/64, M_TOK/128), 256>>>(
        ao, projw, projb, x, x2, 256, 256);
    // 5. LN2
    ln_kernel<<<M_TOK/8, 256>>>(x2, n2g, n2b, xn);
    // 6. FC1 + gelu: [131072,256] @ [1024,256]^T
    gemm_kernel<true,false><<<dim3(1024/64, M_TOK/128), 256>>>(
        xn, fc1w, fc1b, nullptr, hid, 1024, 256);
    // 7. FC2 + residual(x2): [131072,1024] @ [256,1024]^T -> d_out
    gemm_kernel<false,true><<<dim3(256/64, M_TOK/128), 256>>>(
        hid, fc2w, fc2b, x2, out, 256, 1024);
}

// round 3
// speedup vs baseline: 2.0497x; 2.0497x over previous
#include <cuda_runtime.h>
#include <cuda_bf16.h>
#include <cstdint>
#include <cmath>

// ===========================================================================
// SwinTransformerBlock on GB300 (family-portable PTX path, mma.sync bf16).
// B=8, H=W=128, C=256, heads=8, d=32, ws=8, shift=4. M = 131072 tokens.
// Numeric scheme: fp32 operands stored as hi/lo bf16 concatenated along K:
//   cols [0,K) = bf16(x), cols [K,2K) = bf16(x - hi).
//   A plain bf16 GEMM over K' = 2K with fp32 accumulation then computes
//   (Ahi+Alo)(Bhi+Blo): relative error ~2^-16 (fp32-grade).
// ===========================================================================

#define MT 131072

__device__ __align__(16) __nv_bfloat16 g_xni [(size_t)MT*512];    // LN out, K'=512
__device__ float                       g_qkv [(size_t)MT*768];    // qkv fp32
__device__ __align__(16) __nv_bfloat16 g_aoi [(size_t)MT*512];    // attn out, K'=512
__device__ float                       g_x2  [(size_t)MT*256];    // residual-1 fp32
__device__ __align__(16) __nv_bfloat16 g_hidi[(size_t)MT*2048];   // hidden, K'=2048
__device__ __align__(16) __nv_bfloat16 g_qkvwi[768*512];
__device__ __align__(16) __nv_bfloat16 g_projwi[256*512];
__device__ __align__(16) __nv_bfloat16 g_fc1wi[1024*512];
__device__ __align__(16) __nv_bfloat16 g_fc2wi[256*2048];

// ---------------------------------------------------------------------------
__device__ __forceinline__ uint32_t smem_u32(const void* p) {
    uint32_t a;
    asm("{ .reg .u64 t; cvta.to.shared.u64 t, %1; cvt.u32.u64 %0, t; }" : "=r"(a) : "l"(p));
    return a;
}
#define CP_ASYNC16(sa, ga) \
    asm volatile("cp.async.cg.shared.global [%0], [%1], 16;" :: "r"(sa), "l"(ga))
#define CP_COMMIT() asm volatile("cp.async.commit_group;" ::: "memory")
#define CP_WAIT1()  asm volatile("cp.async.wait_group 1;" ::: "memory")

#define LDSM_X4(r0,r1,r2,r3, a) \
    asm volatile("ldmatrix.sync.aligned.m8n8.x4.shared.b16 {%0,%1,%2,%3}, [%4];" \
        : "=r"(r0), "=r"(r1), "=r"(r2), "=r"(r3) : "r"(a))

#define MMA16816(c, a, b0, b1) \
    asm volatile("mma.sync.aligned.m16n8k16.row.col.f32.bf16.bf16.f32 " \
        "{%0,%1,%2,%3}, {%4,%5,%6,%7}, {%8,%9}, {%0,%1,%2,%3};" \
        : "+f"((c)[0]), "+f"((c)[1]), "+f"((c)[2]), "+f"((c)[3]) \
        : "r"((a)[0]), "r"((a)[1]), "r"((a)[2]), "r"((a)[3]), "r"(b0), "r"(b1))

// write 4 consecutive fp32 as hi bf16 at p_hi, residual lo at p_lo
__device__ __forceinline__ void store_hilo4(__nv_bfloat16* p_hi, __nv_bfloat16* p_lo, float4 v) {
    __nv_bfloat16 h[4], l[4];
    h[0] = __float2bfloat16(v.x); l[0] = __float2bfloat16(v.x - __bfloat162float(h[0]));
    h[1] = __float2bfloat16(v.y); l[1] = __float2bfloat16(v.y - __bfloat162float(h[1]));
    h[2] = __float2bfloat16(v.z); l[2] = __float2bfloat16(v.z - __bfloat162float(h[2]));
    h[3] = __float2bfloat16(v.w); l[3] = __float2bfloat16(v.w - __bfloat162float(h[3]));
    *(uint2*)p_hi = *(uint2*)h;
    *(uint2*)p_lo = *(uint2*)l;
}
__device__ __forceinline__ void store_hilo2(__nv_bfloat16* p_hi, __nv_bfloat16* p_lo,
                                            float a, float b) {
    __nv_bfloat16 h[2], l[2];
    h[0] = __float2bfloat16(a); l[0] = __float2bfloat16(a - __bfloat162float(h[0]));
    h[1] = __float2bfloat16(b); l[1] = __float2bfloat16(b - __bfloat162float(h[1]));
    *(uint32_t*)p_hi = *(uint32_t*)h;
    *(uint32_t*)p_lo = *(uint32_t*)l;
}

__device__ __forceinline__ float gelu_f(float v) {
    return 0.5f * v * (1.0f + erff(v * 0.7071067811865476f));
}

// ---------------------------------------------------------------------------
// Weight conversion fp32 [N,K] -> hi/lo bf16 [N,2K] (hi cols [0,K), lo [K,2K))
// ---------------------------------------------------------------------------
__global__ void wconv(const float* __restrict__ w, __nv_bfloat16* __restrict__ o,
                      int total4, int K) {
    int i = blockIdx.x * 256 + threadIdx.x;
    if (i >= total4) return;
    int row = i / (K >> 2);
    int c = (i - row * (K >> 2)) * 4;
    float4 v = *(const float4*)(w + (size_t)row * K + c);
    __nv_bfloat16* base = o + (size_t)row * 2 * K;
    store_hilo4(base + c, base + K + c, v);
}

// ---------------------------------------------------------------------------
// LayerNorm (C=256): one warp/row, hi/lo bf16 out [M,512]
// ---------------------------------------------------------------------------
__global__ __launch_bounds__(256) void ln_kernel(
    const float* __restrict__ x, const float* __restrict__ g,
    const float* __restrict__ b, __nv_bfloat16* __restrict__ out)
{
    size_t row = (size_t)blockIdx.x * 8 + (threadIdx.x >> 5);
    int lane = threadIdx.x & 31;
    const float* xr = x + row * 256 + lane * 8;
    float4 v0 = *(const float4*)(xr);
    float4 v1 = *(const float4*)(xr + 4);

    float s  = v0.x+v0.y+v0.z+v0.w + v1.x+v1.y+v1.z+v1.w;
    float sq = v0.x*v0.x+v0.y*v0.y+v0.z*v0.z+v0.w*v0.w
             + v1.x*v1.x+v1.y*v1.y+v1.z*v1.z+v1.w*v1.w;
    #pragma unroll
    for (int o = 16; o > 0; o >>= 1) {
        s  += __shfl_xor_sync(0xffffffffu, s,  o);
        sq += __shfl_xor_sync(0xffffffffu, sq, o);
    }
    float mean = s * (1.0f/256.0f);
    float rstd = rsqrtf(sq * (1.0f/256.0f) - mean*mean + 1e-5f);

    const float4 g0 = *(const float4*)(g + lane*8);
    const float4 g1 = *(const float4*)(g + lane*8 + 4);
    const float4 b0 = *(const float4*)(b + lane*8);
    const float4 b1 = *(const float4*)(b + lane*8 + 4);

    float4 o0, o1;
    o0.x=(v0.x-mean)*rstd*g0.x+b0.x; o0.y=(v0.y-mean)*rstd*g0.y+b0.y;
    o0.z=(v0.z-mean)*rstd*g0.z+b0.z; o0.w=(v0.w-mean)*rstd*g0.w+b0.w;
    o1.x=(v1.x-mean)*rstd*g1.x+b1.x; o1.y=(v1.y-mean)*rstd*g1.y+b1.y;
    o1.z=(v1.z-mean)*rstd*g1.z+b1.z; o1.w=(v1.w-mean)*rstd*g1.w+b1.w;

    int cb = lane * 8;
    __nv_bfloat16* base = out + row * 512;
    store_hilo4(base + cb,     base + 256 + cb,     o0);
    store_hilo4(base + cb + 4, base + 256 + cb + 4, o1);
}

// ---------------------------------------------------------------------------
// bf16 tensor-core GEMM (mma.sync m16n8k16):
// C[M,N] = A[M,K2]bf16 @ B[N,K2]bf16^T (+bias)(+res)(gelu->hi/lo bf16 out)
// CTA 128x128, K-chunk 64, 3-stage cp.async pipeline, 256 threads (8 warps).
// Warp grid 4x2, warp tile 32x64.
// MODE: 0=bias fp32 out; 1=bias+res fp32 out; 2=bias+gelu hi/lo bf16 out.
// ---------------------------------------------------------------------------
#define HSTAGE 32768        // 16KB A + 16KB B per stage
#define HSMEM  (3*HSTAGE)

template<int MODE>
__global__ __launch_bounds__(256) void hgemm(
    const __nv_bfloat16* __restrict__ A, const __nv_bfloat16* __restrict__ B,
    const float* __restrict__ bias, const float* __restrict__ res,
    void* __restrict__ Cout, int N, int K2)
{
    extern __shared__ char sm[];
    const uint32_t sbase = smem_u32(sm);
    const int tid  = threadIdx.x;
    const int lane = tid & 31;
    const int warp = tid >> 5;
    const int wr   = warp >> 1;          // 0..3  (m block of 32)
    const int wc   = warp & 1;           // 0..1  (n block of 64)
    const size_t gr0 = (size_t)blockIdx.y * 128;
    const int    gc0 = blockIdx.x * 128;
    const int CCH = K2 >> 6;

    const int lrow = tid >> 3;           // 0..31
    const int lkc  = tid & 7;            // 16B chunk within 128B row

    auto load_stage = [&](int c) {
        uint32_t sA = sbase + (c % 3) * HSTAGE;
        uint32_t sB = sA + 16384;
        const __nv_bfloat16* Ab = A + c*64 + lkc*8;
        const __nv_bfloat16* Bb = B + c*64 + lkc*8;
        #pragma unroll
        for (int p = 0; p < 4; p++) {
            int row = lrow + p*32;
            uint32_t off = row*128 + (((uint32_t)(lkc ^ (row & 7))) << 4);
            CP_ASYNC16(sA + off, Ab + (gr0 + row) * (size_t)K2);
            CP_ASYNC16(sB + off, Bb + (size_t)(gc0 + row) * K2);
        }
    };

    load_stage(0); CP_COMMIT();
    load_stage(1); CP_COMMIT();

    float acc[2][8][4];
    #pragma unroll
    for (int mt = 0; mt < 2; mt++)
        #pragma unroll
        for (int nt = 0; nt < 8; nt++)
            #pragma unroll
            for (int q = 0; q < 4; q++) acc[mt][nt][q] = 0.0f;

    const int lr8  = (lane & 7) + ((lane >> 3) & 1) * 8;  // row within 16-tile
    const int lkhi = lane >> 4;                            // 16B half select

    for (int c = 0; c < CCH; c++) {
        CP_WAIT1();
        __syncthreads();
        if (c + 2 < CCH) load_stage(c + 2);
        CP_COMMIT();

        uint32_t sA = sbase + (c % 3) * HSTAGE;
        uint32_t sB = sA + 16384;

        #pragma unroll
        for (int ks = 0; ks < 4; ks++) {
            uint32_t a[2][4];
            #pragma unroll
            for (int mt = 0; mt < 2; mt++) {
                int row = wr*32 + mt*16 + lr8;
                int kc  = 2*ks + lkhi;
                LDSM_X4(a[mt][0], a[mt][1], a[mt][2], a[mt][3],
                        sA + row*128 + ((uint32_t)(kc ^ (row & 7)) << 4));
            }
            uint32_t b[4][4];
            #pragma unroll
            for (int nq = 0; nq < 4; nq++) {
                int row = wc*64 + nq*16 + lr8;
                int kc  = 2*ks + lkhi;
                LDSM_X4(b[nq][0], b[nq][1], b[nq][2], b[nq][3],
                        sB + row*128 + ((uint32_t)(kc ^ (row & 7)) << 4));
            }
            #pragma unroll
            for (int mt = 0; mt < 2; mt++)
                #pragma unroll
                for (int nt = 0; nt < 8; nt++)
                    MMA16816(acc[mt][nt], a[mt], b[nt>>1][nt&1], b[nt>>1][2+(nt&1)]);
        }
        __syncthreads();
    }

    // ---- epilogue: direct fragment stores ----
    const int mrow = lane >> 2;
    const int ncol = (lane & 3) * 2;
    #pragma unroll
    for (int mt = 0; mt < 2; mt++) {
        #pragma unroll
        for (int half = 0; half < 2; half++) {
            size_t grow = gr0 + wr*32 + mt*16 + mrow + half*8;
            #pragma unroll
            for (int nt = 0; nt < 8; nt++) {
                int gcol = gc0 + wc*64 + nt*8 + ncol;
                float v0 = acc[mt][nt][half*2]     + bias[gcol];
                float v1 = acc[mt][nt][half*2 + 1] + bias[gcol + 1];
                if (MODE == 1) {
                    const float* rp = res + grow * (size_t)N + gcol;
                    v0 += rp[0]; v1 += rp[1];
                }
                if (MODE == 2) {
                    v0 = gelu_f(v0); v1 = gelu_f(v1);
                    __nv_bfloat16* base = (__nv_bfloat16*)Cout + grow * (size_t)(2*N);
                    store_hilo2(base + gcol, base + N + gcol, v0, v1);
                } else {
                    float* cp = (float*)Cout + grow * (size_t)N + gcol;
                    cp[0] = v0; cp[1] = v1;
                }
            }
        }
    }
}

// ---------------------------------------------------------------------------
// Fused shifted-window attention (fp32). One block per (window, head).
// Reads qkv fp32; writes hi/lo bf16 (cols [0,256) hi, [256,512) lo).
// ---------------------------------------------------------------------------
__global__ __launch_bounds__(256) void attn_kernel(
    const float* __restrict__ qkv, const float* __restrict__ mask,
    const float* __restrict__ bt, __nv_bfloat16* __restrict__ aoi)
{
    __shared__ __align__(16) float sq[64*32];
    __shared__ __align__(16) float sk[64*32];
    __shared__ __align__(16) float sv[64*32];
    __shared__ float ss[64*65];

    const int head = blockIdx.x;
    const int w    = blockIdx.y;
    const int bimg = w >> 8;
    const int wimg = w & 255;
    const int wh   = wimg >> 4;
    const int ww   = wimg & 15;
    const int tid  = threadIdx.x;

    for (int f = tid; f < 1536; f += 256) {
        int matn = f >> 9;
        int r    = (f >> 3) & 63;
        int c4   = f & 7;
        int i = r >> 3, j = r & 7;
        int oh = (wh*8 + i + 4) & 127;
        int ow = (ww*8 + j + 4) & 127;
        size_t tok = (size_t)bimg * 16384 + oh * 128 + ow;
        float4 v = *(const float4*)(qkv + tok*768 + matn*256 + head*32 + c4*4);
        float* dst = (matn == 0 ? sq : (matn == 1 ? sk : sv)) + r*32 + c4*4;
        *(float4*)dst = v;
    }
    __syncthreads();

    const int tn = (tid >> 4) * 4;
    const int tm = (tid & 15) * 4;
    float acc[4][4];
    #pragma unroll
    for (int i = 0; i < 4; i++)
        #pragma unroll
        for (int j = 0; j < 4; j++) acc[i][j] = 0.0f;

    #pragma unroll
    for (int d4 = 0; d4 < 8; d4++) {
        float4 qv[4], kv[4];
        #pragma unroll
        for (int i = 0; i < 4; i++) qv[i] = *(const float4*)&sq[(tn+i)*32 + d4*4];
        #pragma unroll
        for (int j = 0; j < 4; j++) kv[j] = *(const float4*)&sk[(tm+j)*32 + d4*4];
        #pragma unroll
        for (int i = 0; i < 4; i++)
            #pragma unroll
            for (int j = 0; j < 4; j++)
                acc[i][j] += qv[i].x*kv[j].x + qv[i].y*kv[j].y
                           + qv[i].z*kv[j].z + qv[i].w*kv[j].w;
    }

    const float scale = 0.17677669529663689f;
    const float* mrow = mask + (size_t)wimg * 4096;
    #pragma unroll
    for (int i = 0; i < 4; i++)
        #pragma unroll
        for (int j = 0; j < 4; j++) {
            int n = tn + i, m = tm + j;
            int ridx = ((n>>3) - (m>>3) + 7) * 15 + ((n&7) - (m&7) + 7);
            ss[n*65 + m] = acc[i][j]*scale + bt[ridx*8 + head] + mrow[n*64 + m];
        }
    __syncthreads();

    if (tid < 64) {
        float* r = &ss[tid*65];
        float mx = r[0];
        #pragma unroll 8
        for (int m = 1; m < 64; m++) mx = fmaxf(mx, r[m]);
        float sum = 0.0f;
        #pragma unroll 8
        for (int m = 0; m < 64; m++) { float e = __expf(r[m]-mx); r[m] = e; sum += e; }
        float inv = 1.0f / sum;
        #pragma unroll 8
        for (int m = 0; m < 64; m++) r[m] *= inv;
    }
    __syncthreads();

    for (int u = tid; u < 512; u += 256) {
        int n = u >> 3, dd4 = u & 7;
        float4 a = make_float4(0.f, 0.f, 0.f, 0.f);
        #pragma unroll 8
        for (int m = 0; m < 64; m++) {
            float wgt = ss[n*65 + m];
            float4 vv = *(const float4*)&sv[m*32 + dd4*4];
            a.x += wgt*vv.x; a.y += wgt*vv.y; a.z += wgt*vv.z; a.w += wgt*vv.w;
        }
        int i = n >> 3, j = n & 7;
        int oh = (wh*8 + i + 4) & 127;
        int ow = (ww*8 + j + 4) & 127;
        size_t tok = (size_t)bimg * 16384 + oh * 128 + ow;
        int col = head*32 + dd4*4;
        __nv_bfloat16* base = aoi + tok*512;
        store_hilo4(base + col, base + 256 + col, a);
    }
}

// ---------------------------------------------------------------------------
extern "C" void kernel_launch(void* const* d_in, const int* in_sizes, int n_in,
                              void* d_out, int out_size)
{
    const float* x     = (const float*)d_in[0];
    const float* mask  = (const float*)d_in[1];
    const float* n1g   = (const float*)d_in[2];
    const float* n1b   = (const float*)d_in[3];
    const float* qkvw  = (const float*)d_in[4];
    const float* qkvb  = (const float*)d_in[5];
    const float* relb  = (const float*)d_in[6];
    const float* projw = (const float*)d_in[7];
    const float* projb = (const float*)d_in[8];
    const float* n2g   = (const float*)d_in[9];
    const float* n2b   = (const float*)d_in[10];
    const float* fc1w  = (const float*)d_in[11];
    const float* fc1b  = (const float*)d_in[12];
    const float* fc2w  = (const float*)d_in[13];
    const float* fc2b  = (const float*)d_in[14];
    float* out = (float*)d_out;

    __nv_bfloat16 *xni, *aoi, *hidi, *qkvwi, *projwi, *fc1wi, *fc2wi;
    float *qkv, *x2;
    cudaGetSymbolAddress((void**)&xni,   g_xni);
    cudaGetSymbolAddress((void**)&qkv,   g_qkv);
    cudaGetSymbolAddress((void**)&aoi,   g_aoi);
    cudaGetSymbolAddress((void**)&x2,    g_x2);
    cudaGetSymbolAddress((void**)&hidi,  g_hidi);
    cudaGetSymbolAddress((void**)&qkvwi, g_qkvwi);
    cudaGetSymbolAddress((void**)&projwi,g_projwi);
    cudaGetSymbolAddress((void**)&fc1wi, g_fc1wi);
    cudaGetSymbolAddress((void**)&fc2wi, g_fc2wi);

    cudaFuncSetAttribute(hgemm<0>, cudaFuncAttributeMaxDynamicSharedMemorySize, HSMEM);
    cudaFuncSetAttribute(hgemm<1>, cudaFuncAttributeMaxDynamicSharedMemorySize, HSMEM);
    cudaFuncSetAttribute(hgemm<2>, cudaFuncAttributeMaxDynamicSharedMemorySize, HSMEM);

    // weight conversions (cheap)
    wconv<<<(768*64 + 255)/256, 256>>>(qkvw,  qkvwi,  768*64, 256);
    wconv<<<(256*64 + 255)/256, 256>>>(projw, projwi, 256*64, 256);
    wconv<<<(1024*64 + 255)/256, 256>>>(fc1w, fc1wi, 1024*64, 256);
    wconv<<<(256*256 + 255)/256, 256>>>(fc2w, fc2wi, 256*256, 1024);

    // 1. LN1
    ln_kernel<<<MT/8, 256>>>(x, n1g, n1b, xni);
    // 2. QKV: [131072,512] @ [768,512]^T -> fp32
    hgemm<0><<<dim3(6, MT/128), 256, HSMEM>>>(xni, qkvwi, qkvb, nullptr, qkv, 768, 512);
    // 3. windowed attention
    attn_kernel<<<dim3(8, 2048), 256>>>(qkv, mask, relb, aoi);
    // 4. proj + residual(x) -> x2
    hgemm<1><<<dim3(2, MT/128), 256, HSMEM>>>(aoi, projwi, projb, x, x2, 256, 512);
    // 5. LN2
    ln_kernel<<<MT/8, 256>>>(x2, n2g, n2b, xni);
    // 6. FC1 + gelu -> hidden (hi/lo bf16)
    hgemm<2><<<dim3(8, MT/128), 256, HSMEM>>>(xni, fc1wi, fc1b, nullptr, hidi, 1024, 512);
    // 7. FC2 + residual(x2) -> out
    hgemm<1><<<dim3(2, MT/128), 256, HSMEM>>>(hidi, fc2wi, fc2b, x2, out, 256, 2048);
}

// round 4
// speedup vs baseline: 2.3617x; 1.1522x over previous
#include <cuda_runtime.h>
#include <cuda_bf16.h>
#include <cstdint>
#include <cmath>

// ===========================================================================
// SwinTransformerBlock on GB300 (family-portable PTX path, mma.sync bf16).
// B=8, H=W=128, C=256, heads=8, d=32, ws=8, shift=4. M = 131072 tokens.
// fp32 operands stored as hi/lo bf16 concatenated along K:
//   cols [0,K) = bf16(x), cols [K,2K) = bf16(x - hi); plain bf16 GEMM over
//   K' = 2K with fp32 accumulation -> rel error ~2^-16.
// R4: occupancy-2 GEMM, earlier cp.async issue, smem-staged coalesced epilogue.
// ===========================================================================

#define MT 131072

__device__ __align__(16) __nv_bfloat16 g_xni [(size_t)MT*512];
__device__ float                       g_qkv [(size_t)MT*768];
__device__ __align__(16) __nv_bfloat16 g_aoi [(size_t)MT*512];
__device__ float                       g_x2  [(size_t)MT*256];
__device__ __align__(16) __nv_bfloat16 g_hidi[(size_t)MT*2048];
__device__ __align__(16) __nv_bfloat16 g_qkvwi[768*512];
__device__ __align__(16) __nv_bfloat16 g_projwi[256*512];
__device__ __align__(16) __nv_bfloat16 g_fc1wi[1024*512];
__device__ __align__(16) __nv_bfloat16 g_fc2wi[256*2048];

// ---------------------------------------------------------------------------
__device__ __forceinline__ uint32_t smem_u32(const void* p) {
    uint32_t a;
    asm("{ .reg .u64 t; cvta.to.shared.u64 t, %1; cvt.u32.u64 %0, t; }" : "=r"(a) : "l"(p));
    return a;
}
#define CP_ASYNC16(sa, ga) \
    asm volatile("cp.async.cg.shared.global [%0], [%1], 16;" :: "r"(sa), "l"(ga))
#define CP_COMMIT() asm volatile("cp.async.commit_group;" ::: "memory")
#define CP_WAIT2()  asm volatile("cp.async.wait_group 2;" ::: "memory")
#define CP_WAIT0()  asm volatile("cp.async.wait_group 0;" ::: "memory")

#define LDSM_X4(r0,r1,r2,r3, a) \
    asm volatile("ldmatrix.sync.aligned.m8n8.x4.shared.b16 {%0,%1,%2,%3}, [%4];" \
        : "=r"(r0), "=r"(r1), "=r"(r2), "=r"(r3) : "r"(a))

#define MMA16816(c, a, b0, b1) \
    asm volatile("mma.sync.aligned.m16n8k16.row.col.f32.bf16.bf16.f32 " \
        "{%0,%1,%2,%3}, {%4,%5,%6,%7}, {%8,%9}, {%0,%1,%2,%3};" \
        : "+f"((c)[0]), "+f"((c)[1]), "+f"((c)[2]), "+f"((c)[3]) \
        : "r"((a)[0]), "r"((a)[1]), "r"((a)[2]), "r"((a)[3]), "r"(b0), "r"(b1))

__device__ __forceinline__ void store_hilo4(__nv_bfloat16* p_hi, __nv_bfloat16* p_lo, float4 v) {
    __nv_bfloat16 h[4], l[4];
    h[0] = __float2bfloat16(v.x); l[0] = __float2bfloat16(v.x - __bfloat162float(h[0]));
    h[1] = __float2bfloat16(v.y); l[1] = __float2bfloat16(v.y - __bfloat162float(h[1]));
    h[2] = __float2bfloat16(v.z); l[2] = __float2bfloat16(v.z - __bfloat162float(h[2]));
    h[3] = __float2bfloat16(v.w); l[3] = __float2bfloat16(v.w - __bfloat162float(h[3]));
    *(uint2*)p_hi = *(uint2*)h;
    *(uint2*)p_lo = *(uint2*)l;
}

__device__ __forceinline__ float gelu_f(float v) {
    return 0.5f * v * (1.0f + erff(v * 0.7071067811865476f));
}

// ---------------------------------------------------------------------------
// Combined weight conversion (all 4 weights in one launch).
// fp32 [N,K] -> hi/lo bf16 [N,2K]
// ---------------------------------------------------------------------------
struct WJob { const float* w; __nv_bfloat16* o; int quads; int K; int qoff; };
__global__ void wconv_all(const float* w0, __nv_bfloat16* o0,
                          const float* w1, __nv_bfloat16* o1,
                          const float* w2, __nv_bfloat16* o2,
                          const float* w3, __nv_bfloat16* o3) {
    int i = blockIdx.x * 256 + threadIdx.x;
    // ranges (quads of 4 floats): qkv 49152, proj 16384, fc1 65536, fc2 65536
    const float* w; __nv_bfloat16* o; int K; int li;
    if (i < 49152)        { w = w0; o = o0; K = 256;  li = i; }
    else if (i < 65536)   { w = w1; o = o1; K = 256;  li = i - 49152; }
    else if (i < 131072)  { w = w2; o = o2; K = 256;  li = i - 65536; }
    else if (i < 196608)  { w = w3; o = o3; K = 1024; li = i - 131072; }
    else return;
    int row = li / (K >> 2);
    int c = (li - row * (K >> 2)) * 4;
    float4 v = *(const float4*)(w + (size_t)row * K + c);
    __nv_bfloat16* base = o + (size_t)row * 2 * K;
    store_hilo4(base + c, base + K + c, v);
}

// ---------------------------------------------------------------------------
// LayerNorm (C=256): one warp/row, hi/lo bf16 out [M,512]
// ---------------------------------------------------------------------------
__global__ __launch_bounds__(256) void ln_kernel(
    const float* __restrict__ x, const float* __restrict__ g,
    const float* __restrict__ b, __nv_bfloat16* __restrict__ out)
{
    size_t row = (size_t)blockIdx.x * 8 + (threadIdx.x >> 5);
    int lane = threadIdx.x & 31;
    const float* xr = x + row * 256 + lane * 8;
    float4 v0 = *(const float4*)(xr);
    float4 v1 = *(const float4*)(xr + 4);

    float s  = v0.x+v0.y+v0.z+v0.w + v1.x+v1.y+v1.z+v1.w;
    float sq = v0.x*v0.x+v0.y*v0.y+v0.z*v0.z+v0.w*v0.w
             + v1.x*v1.x+v1.y*v1.y+v1.z*v1.z+v1.w*v1.w;
    #pragma unroll
    for (int o = 16; o > 0; o >>= 1) {
        s  += __shfl_xor_sync(0xffffffffu, s,  o);
        sq += __shfl_xor_sync(0xffffffffu, sq, o);
    }
    float mean = s * (1.0f/256.0f);
    float rstd = rsqrtf(sq * (1.0f/256.0f) - mean*mean + 1e-5f);

    const float4 g0 = *(const float4*)(g + lane*8);
    const float4 g1 = *(const float4*)(g + lane*8 + 4);
    const float4 b0 = *(const float4*)(b + lane*8);
    const float4 b1 = *(const float4*)(b + lane*8 + 4);

    float4 o0, o1;
    o0.x=(v0.x-mean)*rstd*g0.x+b0.x; o0.y=(v0.y-mean)*rstd*g0.y+b0.y;
    o0.z=(v0.z-mean)*rstd*g0.z+b0.z; o0.w=(v0.w-mean)*rstd*g0.w+b0.w;
    o1.x=(v1.x-mean)*rstd*g1.x+b1.x; o1.y=(v1.y-mean)*rstd*g1.y+b1.y;
    o1.z=(v1.z-mean)*rstd*g1.z+b1.z; o1.w=(v1.w-mean)*rstd*g1.w+b1.w;

    int cb = lane * 8;
    __nv_bfloat16* base = out + row * 512;
    store_hilo4(base + cb,     base + 256 + cb,     o0);
    store_hilo4(base + cb + 4, base + 256 + cb + 4, o1);
}

// ---------------------------------------------------------------------------
// bf16 tensor-core GEMM (mma.sync m16n8k16), CTA 128x128, K-chunk 64,
// 3-stage cp.async pipeline, 256 threads (8 warps, 4x2), 2 CTAs/SM.
// MODE: 0=bias fp32 out; 1=bias+res fp32 out; 2=bias+gelu hi/lo bf16 out.
// ---------------------------------------------------------------------------
#define HSTAGE 32768
#define HSMEM  (3*HSTAGE)

template<int MODE>
__global__ __launch_bounds__(256, 2) void hgemm(
    const __nv_bfloat16* __restrict__ A, const __nv_bfloat16* __restrict__ B,
    const float* __restrict__ bias, const float* __restrict__ res,
    void* __restrict__ Cout, int N, int K2)
{
    extern __shared__ char sm[];
    const uint32_t sbase = smem_u32(sm);
    const int tid  = threadIdx.x;
    const int lane = tid & 31;
    const int warp = tid >> 5;
    const int wr   = warp >> 1;
    const int wc   = warp & 1;
    const size_t gr0 = (size_t)blockIdx.y * 128;
    const int    gc0 = blockIdx.x * 128;
    const int CCH = K2 >> 6;

    const int lrow = tid >> 3;
    const int lkc  = tid & 7;

    auto load_stage = [&](int c) {
        uint32_t sA = sbase + (c % 3) * HSTAGE;
        uint32_t sB = sA + 16384;
        const __nv_bfloat16* Ab = A + c*64 + lkc*8;
        const __nv_bfloat16* Bb = B + c*64 + lkc*8;
        #pragma unroll
        for (int p = 0; p < 4; p++) {
            int row = lrow + p*32;
            uint32_t off = row*128 + (((uint32_t)(lkc ^ (row & 7))) << 4);
            CP_ASYNC16(sA + off, Ab + (gr0 + row) * (size_t)K2);
            CP_ASYNC16(sB + off, Bb + (size_t)(gc0 + row) * K2);
        }
    };

    load_stage(0); CP_COMMIT();
    load_stage(1); CP_COMMIT();

    float acc[2][8][4];
    #pragma unroll
    for (int mt = 0; mt < 2; mt++)
        #pragma unroll
        for (int nt = 0; nt < 8; nt++)
            #pragma unroll
            for (int q = 0; q < 4; q++) acc[mt][nt][q] = 0.0f;

    const int lr8  = (lane & 7) + ((lane >> 3) & 1) * 8;
    const int lkhi = lane >> 4;

    for (int c = 0; c < CCH; c++) {
        if (c + 2 < CCH) { load_stage(c + 2); }
        CP_COMMIT();
        CP_WAIT2();                 // chunk c's data resident
        __syncthreads();

        uint32_t sA = sbase + (c % 3) * HSTAGE;
        uint32_t sB = sA + 16384;

        #pragma unroll
        for (int ks = 0; ks < 4; ks++) {
            uint32_t a[2][4];
            #pragma unroll
            for (int mt = 0; mt < 2; mt++) {
                int row = wr*32 + mt*16 + lr8;
                int kc  = 2*ks + lkhi;
                LDSM_X4(a[mt][0], a[mt][1], a[mt][2], a[mt][3],
                        sA + row*128 + ((uint32_t)(kc ^ (row & 7)) << 4));
            }
            uint32_t b[4][4];
            #pragma unroll
            for (int nq = 0; nq < 4; nq++) {
                int row = wc*64 + nq*16 + lr8;
                int kc  = 2*ks + lkhi;
                LDSM_X4(b[nq][0], b[nq][1], b[nq][2], b[nq][3],
                        sB + row*128 + ((uint32_t)(kc ^ (row & 7)) << 4));
            }
            #pragma unroll
            for (int mt = 0; mt < 2; mt++)
                #pragma unroll
                for (int nt = 0; nt < 8; nt++)
                    MMA16816(acc[mt][nt], a[mt], b[nt>>1][nt&1], b[nt>>1][2+(nt&1)]);
        }
        __syncthreads();
    }

    // ---- epilogue: stage fragments through smem, coalesced global stores ----
    CP_WAIT0();
    float* epi = (float*)sm;        // 128 x 132 fp32 = 67.5 KB (buffers free now)
    const int mrow = lane >> 2;
    const int ncol = (lane & 3) * 2;
    #pragma unroll
    for (int mt = 0; mt < 2; mt++)
        #pragma unroll
        for (int half = 0; half < 2; half++) {
            int r = wr*32 + mt*16 + half*8 + mrow;
            #pragma unroll
            for (int nt = 0; nt < 8; nt++) {
                int cc = wc*64 + nt*8 + ncol;
                *(float2*)&epi[r*132 + cc] =
                    make_float2(acc[mt][nt][half*2], acc[mt][nt][half*2+1]);
            }
        }
    __syncthreads();

    #pragma unroll 4
    for (int it = 0; it < 16; it++) {
        int idx = it*256 + tid;
        int row = idx >> 5;
        int c4  = (idx & 31) * 4;
        int gcol = gc0 + c4;
        float4 v = *(float4*)&epi[row*132 + c4];
        float4 bb = *(const float4*)(bias + gcol);
        v.x += bb.x; v.y += bb.y; v.z += bb.z; v.w += bb.w;
        size_t grow = gr0 + row;
        if (MODE == 1) {
            float4 r = *(const float4*)(res + grow * (size_t)N + gcol);
            v.x += r.x; v.y += r.y; v.z += r.z; v.w += r.w;
        }
        if (MODE == 2) {
            v.x = gelu_f(v.x); v.y = gelu_f(v.y); v.z = gelu_f(v.z); v.w = gelu_f(v.w);
            __nv_bfloat16* base = (__nv_bfloat16*)Cout + grow * (size_t)(2*N);
            store_hilo4(base + gcol, base + N + gcol, v);
        } else {
            *(float4*)((float*)Cout + grow * (size_t)N + gcol) = v;
        }
    }
}

// ---------------------------------------------------------------------------
// Fused shifted-window attention (fp32). One block per (window, head).
// ---------------------------------------------------------------------------
__global__ __launch_bounds__(256) void attn_kernel(
    const float* __restrict__ qkv, const float* __restrict__ mask,
    const float* __restrict__ bt, __nv_bfloat16* __restrict__ aoi)
{
    __shared__ __align__(16) float sq[64*32];
    __shared__ __align__(16) float sk[64*32];
    __shared__ __align__(16) float sv[64*32];
    __shared__ float ss[64*65];

    const int head = blockIdx.x;
    const int w    = blockIdx.y;
    const int bimg = w >> 8;
    const int wimg = w & 255;
    const int wh   = wimg >> 4;
    const int ww   = wimg & 15;
    const int tid  = threadIdx.x;

    for (int f = tid; f < 1536; f += 256) {
        int matn = f >> 9;
        int r    = (f >> 3) & 63;
        int c4   = f & 7;
        int i = r >> 3, j = r & 7;
        int oh = (wh*8 + i + 4) & 127;
        int ow = (ww*8 + j + 4) & 127;
        size_t tok = (size_t)bimg * 16384 + oh * 128 + ow;
        float4 v = *(const float4*)(qkv + tok*768 + matn*256 + head*32 + c4*4);
        float* dst = (matn == 0 ? sq : (matn == 1 ? sk : sv)) + r*32 + c4*4;
        *(float4*)dst = v;
    }
    __syncthreads();

    const int tn = (tid >> 4) * 4;
    const int tm = (tid & 15) * 4;
    float acc[4][4];
    #pragma unroll
    for (int i = 0; i < 4; i++)
        #pragma unroll
        for (int j = 0; j < 4; j++) acc[i][j] = 0.0f;

    #pragma unroll
    for (int d4 = 0; d4 < 8; d4++) {
        float4 qv[4], kv[4];
        #pragma unroll
        for (int i = 0; i < 4; i++) qv[i] = *(const float4*)&sq[(tn+i)*32 + d4*4];
        #pragma unroll
        for (int j = 0; j < 4; j++) kv[j] = *(const float4*)&sk[(tm+j)*32 + d4*4];
        #pragma unroll
        for (int i = 0; i < 4; i++)
            #pragma unroll
            for (int j = 0; j < 4; j++)
                acc[i][j] += qv[i].x*kv[j].x + qv[i].y*kv[j].y
                           + qv[i].z*kv[j].z + qv[i].w*kv[j].w;
    }

    const float scale = 0.17677669529663689f;
    const float* mrow = mask + (size_t)wimg * 4096;
    #pragma unroll
    for (int i = 0; i < 4; i++)
        #pragma unroll
        for (int j = 0; j < 4; j++) {
            int n = tn + i, m = tm + j;
            int ridx = ((n>>3) - (m>>3) + 7) * 15 + ((n&7) - (m&7) + 7);
            ss[n*65 + m] = acc[i][j]*scale + bt[ridx*8 + head] + mrow[n*64 + m];
        }
    __syncthreads();

    if (tid < 64) {
        float* r = &ss[tid*65];
        float mx = r[0];
        #pragma unroll 8
        for (int m = 1; m < 64; m++) mx = fmaxf(mx, r[m]);
        float sum = 0.0f;
        #pragma unroll 8
        for (int m = 0; m < 64; m++) { float e = __expf(r[m]-mx); r[m] = e; sum += e; }
        float inv = 1.0f / sum;
        #pragma unroll 8
        for (int m = 0; m < 64; m++) r[m] *= inv;
    }
    __syncthreads();

    for (int u = tid; u < 512; u += 256) {
        int n = u >> 3, dd4 = u & 7;
        float4 a = make_float4(0.f, 0.f, 0.f, 0.f);
        #pragma unroll 8
        for (int m = 0; m < 64; m++) {
            float wgt = ss[n*65 + m];
            float4 vv = *(const float4*)&sv[m*32 + dd4*4];
            a.x += wgt*vv.x; a.y += wgt*vv.y; a.z += wgt*vv.z; a.w += wgt*vv.w;
        }
        int i = n >> 3, j = n & 7;
        int oh = (wh*8 + i + 4) & 127;
        int ow = (ww*8 + j + 4) & 127;
        size_t tok = (size_t)bimg * 16384 + oh * 128 + ow;
        int col = head*32 + dd4*4;
        __nv_bfloat16* base = aoi + tok*512;
        store_hilo4(base + col, base + 256 + col, a);
    }
}

// ---------------------------------------------------------------------------
extern "C" void kernel_launch(void* const* d_in, const int* in_sizes, int n_in,
                              void* d_out, int out_size)
{
    const float* x     = (const float*)d_in[0];
    const float* mask  = (const float*)d_in[1];
    const float* n1g   = (const float*)d_in[2];
    const float* n1b   = (const float*)d_in[3];
    const float* qkvw  = (const float*)d_in[4];
    const float* qkvb  = (const float*)d_in[5];
    const float* relb  = (const float*)d_in[6];
    const float* projw = (const float*)d_in[7];
    const float* projb = (const float*)d_in[8];
    const float* n2g   = (const float*)d_in[9];
    const float* n2b   = (const float*)d_in[10];
    const float* fc1w  = (const float*)d_in[11];
    const float* fc1b  = (const float*)d_in[12];
    const float* fc2w  = (const float*)d_in[13];
    const float* fc2b  = (const float*)d_in[14];
    float* out = (float*)d_out;

    __nv_bfloat16 *xni, *aoi, *hidi, *qkvwi, *projwi, *fc1wi, *fc2wi;
    float *qkv, *x2;
    cudaGetSymbolAddress((void**)&xni,   g_xni);
    cudaGetSymbolAddress((void**)&qkv,   g_qkv);
    cudaGetSymbolAddress((void**)&aoi,   g_aoi);
    cudaGetSymbolAddress((void**)&x2,    g_x2);
    cudaGetSymbolAddress((void**)&hidi,  g_hidi);
    cudaGetSymbolAddress((void**)&qkvwi, g_qkvwi);
    cudaGetSymbolAddress((void**)&projwi,g_projwi);
    cudaGetSymbolAddress((void**)&fc1wi, g_fc1wi);
    cudaGetSymbolAddress((void**)&fc2wi, g_fc2wi);

    cudaFuncSetAttribute(hgemm<0>, cudaFuncAttributeMaxDynamicSharedMemorySize, HSMEM);
    cudaFuncSetAttribute(hgemm<1>, cudaFuncAttributeMaxDynamicSharedMemorySize, HSMEM);
    cudaFuncSetAttribute(hgemm<2>, cudaFuncAttributeMaxDynamicSharedMemorySize, HSMEM);

    wconv_all<<<768, 256>>>(qkvw, qkvwi, projw, projwi, fc1w, fc1wi, fc2w, fc2wi);

    // 1. LN1
    ln_kernel<<<MT/8, 256>>>(x, n1g, n1b, xni);
    // 2. QKV: [131072,512] @ [768,512]^T -> fp32
    hgemm<0><<<dim3(6, MT/128), 256, HSMEM>>>(xni, qkvwi, qkvb, nullptr, qkv, 768, 512);
    // 3. windowed attention
    attn_kernel<<<dim3(8, 2048), 256>>>(qkv, mask, relb, aoi);
    // 4. proj + residual(x) -> x2
    hgemm<1><<<dim3(2, MT/128), 256, HSMEM>>>(aoi, projwi, projb, x, x2, 256, 512);
    // 5. LN2
    ln_kernel<<<MT/8, 256>>>(x2, n2g, n2b, xni);
    // 6. FC1 + gelu -> hidden (hi/lo bf16)
    hgemm<2><<<dim3(8, MT/128), 256, HSMEM>>>(xni, fc1wi, fc1b, nullptr, hidi, 1024, 512);
    // 7. FC2 + residual(x2) -> out
    hgemm<1><<<dim3(2, MT/128), 256, HSMEM>>>(hidi, fc2wi, fc2b, x2, out, 256, 2048);
}